// round 15
// baseline (speedup 1.0000x reference)
#include <cuda_runtime.h>
#include <stdint.h>

#define NROWS 65536
#define KDIM  2048
#define BM 128
#define BK 32
#define NKT (KDIM / BK)   // 64
#define NPAIR (NKT / 2)   // 32
#define NT  256

// ---------------- device scratch ----------------
__device__ int g_cnt[4];
__device__ int g_perm[4][NROWS];          // 1 MB
__device__ float g_W1T[384 * KDIM];       // 3 MB: W1^T n-major [n][k], tf32 (hedged)
__device__ float g_W2T[20480];            // W2^T n-major [n][k] per expert, tf32

#define W1ROW_SC 0
#define W1ROW_ST 64
#define W1ROW_WM 128
#define W1ROW_CH 256
#define W2OFF_SC 0
#define W2OFF_ST 2048
#define W2OFF_WM 4096
#define W2OFF_CH 12288

// ---------------- helpers ----------------
__device__ __forceinline__ void cp16(uint32_t dst, const float* src) {
    asm volatile("cp.async.ca.shared.global [%0], [%1], 16;\n" :: "r"(dst), "l"(src));
}
__device__ __forceinline__ uint32_t f2tf(float x) {
    uint32_t u; asm("cvt.rna.tf32.f32 %0, %1;" : "=r"(u) : "f"(x)); return u;
}
#define LDSM_X4(R0, R1, R2, R3, ADDR) \
    asm volatile("ldmatrix.sync.aligned.m8n8.x4.shared.b16 {%0,%1,%2,%3}, [%4];" \
        : "=r"(R0), "=r"(R1), "=r"(R2), "=r"(R3) : "r"(ADDR))

// ---------------- prep: transpose + tf32-round W1 (hedged), W2 ----------------
__global__ void prep_kernel(const float* __restrict__ W1_sc, const float* __restrict__ W1_st,
                            const float* __restrict__ W1_wm, const float* __restrict__ W1_ch,
                            const float* __restrict__ W2_sc, const float* __restrict__ W2_st,
                            const float* __restrict__ W2_wm, const float* __restrict__ W2_ch) {
    const int T = 384 * KDIM;
    const float hedge = 1.000244140625f;   // centers tf32-RZ truncation bias of X
    for (int i = blockIdx.x * blockDim.x + threadIdx.x; i < T;
         i += gridDim.x * blockDim.x) {
        int n = i >> 11, k = i & 2047;
        float v;
        if (n < 64)        v = W1_sc[k * 64 + n];
        else if (n < 128)  v = W1_st[k * 64 + (n - 64)];
        else if (n < 256)  v = W1_wm[(size_t)k * 128 + (n - 128)];
        else               v = W1_ch[(size_t)k * 128 + (n - 256)];
        g_W1T[i] = __uint_as_float(f2tf(v * hedge));
    }
    for (int i = blockIdx.x * blockDim.x + threadIdx.x; i < 20480;
         i += gridDim.x * blockDim.x) {
        float v;
        if (i < 2048)       { int j = i;          v = W2_sc[(j & 63) * 32 + (j >> 6)];  }
        else if (i < 4096)  { int j = i - 2048;   v = W2_st[(j & 63) * 32 + (j >> 6)];  }
        else if (i < 12288) { int j = i - 4096;   v = W2_wm[(j & 127) * 64 + (j >> 7)]; }
        else                { int j = i - 12288;  v = W2_ch[(j & 127) * 64 + (j >> 7)]; }
        g_W2T[i] = __uint_as_float(f2tf(v));
    }
}

// ---------------- bucket kernels ----------------
__global__ void zero_cnt_kernel() {
    if (threadIdx.x < 4) g_cnt[threadIdx.x] = 0;
}
__global__ void bucket_kernel(const int* __restrict__ labels, float* __restrict__ out) {
    int r = blockIdx.x * blockDim.x + threadIdx.x;
    if (r >= NROWS) return;
    int lab = labels[r];
    bool valid = (lab >= 0) && (lab <= 3);
    if (!valid) { out[r] = 0.f; lab = -1; }
    int lane = threadIdx.x & 31;
#pragma unroll
    for (int l = 0; l < 4; l++) {
        unsigned mask = __ballot_sync(0xffffffffu, lab == l);
        if (lab == l) {
            int leader = __ffs(mask) - 1;
            int myrank = __popc(mask & ((1u << lane) - 1));
            int basep = 0;
            if (lane == leader) basep = atomicAdd(&g_cnt[l], __popc(mask));
            basep = __shfl_sync(mask, basep, leader);
            g_perm[l][basep + myrank] = r;
        }
    }
}

// smem (floats): A 6x4096 [0,24576) | B 6x(H*32) [24576, +6*BBUF) | tail @49152 (384)
// W2T aliases A stages 0..1 (pair-buffer 0; dead at kp=NPAIR-1).
// h1 aliases the B-stage region (BM*H <= 24576 floats).
#define OFF_B 24576
#define OFF_TAIL 49152
#define SMEM_FLOATS 49536     // 198,144 B -> 1 CTA/SM

// ---------------- fused expert body (256 thr, 8 warps = 4m x 2n, LDSM,
//                  6 stages / 3 pairs, ONE barrier per 2 k-tiles) ----------------
template<int H>
__device__ __forceinline__ void expert_body(
    int e, int chunk, const float* __restrict__ X,
    const float* __restrict__ W1T,   // [H rows][2048], tf32 hedged
    const float* __restrict__ W2T,   // [H2 rows][H], tf32
    const float* __restrict__ b1, const float* __restrict__ b2,
    const float* __restrict__ W3, const float* __restrict__ b3,
    float* __restrict__ out, float* smem)
{
    constexpr int H2   = H / 2;
    constexpr int JB   = H / 16;     // layer-1 n8 blocks/warp (warp n-tile H/2)
    constexpr int JP   = H / 32;     // x4-LDSM pairs
    constexpr int JB2  = H2 / 16;
    constexpr int JP2  = H2 / 32;
    constexpr int ABUF = 4096;
    constexpr int BBUF = H * 32;

    int count = g_cnt[e];
    int base = chunk * BM;
    if (base >= count) return;
    const int* perm = g_perm[e];

    uint32_t sbase = (uint32_t)__cvta_generic_to_shared(smem);
    float* sW3   = smem + OFF_TAIL;
    float* sB2   = smem + OFF_TAIL + 64;
    float* sPart = smem + OFF_TAIL + 128;
    int*   sRow  = (int*)(smem + OFF_TAIL + 256);

    int tid = threadIdx.x, lane = tid & 31, warp = tid >> 5;
    int wm = warp & 3;        // 32 rows each
    int wn = warp >> 2;       // 0..1, H/2 cols each

    if (tid < BM) {
        int idx = base + tid;
        if (idx >= count) idx = count - 1;
        sRow[tid] = perm[idx];
    }
    if (tid < H2) { sW3[tid] = W3[tid]; sB2[tid] = b2[tid]; }
    __syncthreads();

    int rid[4];
#pragma unroll
    for (int it = 0; it < 4; it++) rid[it] = sRow[(tid + it * NT) >> 3];

    float acc[2][JB][4];
#pragma unroll
    for (int i = 0; i < 2; i++)
#pragma unroll
        for (int j = 0; j < JB; j++)
#pragma unroll
            for (int r = 0; r < 4; r++) acc[i][j][r] = 0.f;

    auto loadA = [&](int stg, int kt) {
        uint32_t dbase = sbase + stg * (ABUF * 4);
#pragma unroll
        for (int it = 0; it < 4; it++) {
            int slot = tid + it * NT;
            int r = slot >> 3, c = slot & 7;
            cp16(dbase + r * 128 + ((c ^ (r & 7)) << 4),
                 X + (size_t)rid[it] * KDIM + kt * BK + c * 4);
        }
    };
    auto loadB = [&](int stg, int kt) {
        uint32_t dbase = sbase + (OFF_B + stg * BBUF) * 4;
#pragma unroll
        for (int it = 0; it < (H * 8) / NT; it++) {
            int slot = tid + it * NT;
            int r = slot >> 3, c = slot & 7;
            cp16(dbase + r * 128 + ((c ^ (r & 7)) << 4),
                 W1T + (size_t)r * KDIM + kt * BK + c * 4);
        }
    };
    auto loadW2 = [&]() {     // into A stages 0..1 (smem base)
        constexpr int CQ = H / 4;
#pragma unroll
        for (int it = 0; it < (H2 * CQ) / NT; it++) {
            int slot = tid + it * NT;
            int r = slot / CQ, c = slot % CQ;
            cp16(sbase + r * (H * 4) + ((c ^ (r & 7)) << 4),
                 W2T + (size_t)r * H + c * 4);
        }
    };

    // prologue: pairs 0 and 1 (stages 0..3), one commit group per pair
    loadA(0, 0); loadB(0, 0); loadA(1, 1); loadB(1, 1);
    asm volatile("cp.async.commit_group;\n");
    loadA(2, 2); loadB(2, 2); loadA(3, 3); loadB(3, 3);
    asm volatile("cp.async.commit_group;\n");

    int a_row_in = ((lane >> 3) & 1) * 8 + (lane & 7);
    int a_kq_hi  = lane >> 4;
    int b_row_in = ((lane >> 4) & 1) * 8 + (lane & 7);
    int b_kq_hi  = (lane >> 3) & 1;

    // ONE barrier per PAIR of k-tiles: wait, sync, prefetch pair kp+2, compute 2 ktiles.
    // Pair-buffer (kp+2)%3 == (kp-1)%3 was consumed last iteration (readers passed sync).
    for (int kp = 0; kp < NPAIR; kp++) {
        int pb = kp % 3;
        if (kp < NPAIR - 1) {
            asm volatile("cp.async.wait_group 1;\n");   // pair kp landed
        } else {
            asm volatile("cp.async.wait_group 0;\n");
        }
        __syncthreads();
        if (kp + 2 < NPAIR) {
            int ns = ((kp + 2) % 3) * 2;
            loadA(ns, 2 * (kp + 2));     loadB(ns, 2 * (kp + 2));
            loadA(ns + 1, 2 * (kp + 2) + 1); loadB(ns + 1, 2 * (kp + 2) + 1);
            asm volatile("cp.async.commit_group;\n");
        } else if (kp == NPAIR - 1) {
            loadW2();                                   // A pair-buffer 0 is dead now
            asm volatile("cp.async.commit_group;\n");
        }

#pragma unroll
        for (int half = 0; half < 2; half++) {
            int buf = pb * 2 + half;
            uint32_t Ab = sbase + buf * (ABUF * 4);
            uint32_t Bb = sbase + (OFF_B + buf * BBUF) * 4;

#pragma unroll
            for (int ks = 0; ks < 4; ks++) {
                uint32_t afr[2][4];
#pragma unroll
                for (int i = 0; i < 2; i++) {
                    int row = wm * 32 + i * 16 + a_row_in;
                    int kq  = ks * 2 + a_kq_hi;
                    uint32_t ad = Ab + row * 128 + ((kq ^ (row & 7)) << 4);
                    LDSM_X4(afr[i][0], afr[i][1], afr[i][2], afr[i][3], ad);
                }
                uint32_t bfr[JB][2];
#pragma unroll
                for (int jp = 0; jp < JP; jp++) {
                    int n  = wn * (H / 2) + jp * 16 + b_row_in;
                    int kq = ks * 2 + b_kq_hi;
                    uint32_t bd = Bb + n * 128 + ((kq ^ (n & 7)) << 4);
                    LDSM_X4(bfr[2 * jp][0], bfr[2 * jp][1],
                            bfr[2 * jp + 1][0], bfr[2 * jp + 1][1], bd);
                }
#pragma unroll
                for (int i = 0; i < 2; i++)
#pragma unroll
                    for (int j = 0; j < JB; j++) {
                        asm volatile(
                            "mma.sync.aligned.m16n8k8.row.col.f32.tf32.tf32.f32 "
                            "{%0,%1,%2,%3}, {%4,%5,%6,%7}, {%8,%9}, {%0,%1,%2,%3};\n"
                            : "+f"(acc[i][j][0]), "+f"(acc[i][j][1]),
                              "+f"(acc[i][j][2]), "+f"(acc[i][j][3])
                            : "r"(afr[i][0]), "r"(afr[i][1]),
                              "r"(afr[i][2]), "r"(afr[i][3]),
                              "r"(bfr[j][0]), "r"(bfr[j][1]));
                    }
            }
        }
    }
    __syncthreads();   // all compute done before h1 overwrites B stages

    // ---- layer-1 epilogue: +b1, relu, tf32-round (rna), h1 -> B-stage region ----
    float* h1 = smem + OFF_B;
#pragma unroll
    for (int i = 0; i < 2; i++) {
        int row0 = wm * 32 + i * 16 + (lane >> 2);
        int row1 = row0 + 8;
#pragma unroll
        for (int j = 0; j < JB; j++) {
            int col = wn * (H / 2) + j * 8 + 2 * (lane & 3);
            float bv0 = __ldg(b1 + col), bv1 = __ldg(b1 + col + 1);
            float2 v0, v1;
            v0.x = __uint_as_float(f2tf(fmaxf(acc[i][j][0] + bv0, 0.f)));
            v0.y = __uint_as_float(f2tf(fmaxf(acc[i][j][1] + bv1, 0.f)));
            v1.x = __uint_as_float(f2tf(fmaxf(acc[i][j][2] + bv0, 0.f)));
            v1.y = __uint_as_float(f2tf(fmaxf(acc[i][j][3] + bv1, 0.f)));
            int cq = col >> 2, cr = col & 3;
            *(float2*)((char*)h1 + row0 * (H * 4) + ((cq ^ (row0 & 7)) << 4) + cr * 4) = v0;
            *(float2*)((char*)h1 + row1 * (H * 4) + ((cq ^ (row1 & 7)) << 4) + cr * 4) = v1;
        }
    }
    asm volatile("cp.async.wait_group 0;\n");   // W2T landed (A stages 0..1)
    __syncthreads();

    // ---- layer 2: acc2 = h1 @ W2T^T (LDSM + mma; operands exact tf32) ----
    float acc2[2][JB2][4];
#pragma unroll
    for (int i = 0; i < 2; i++)
#pragma unroll
        for (int j = 0; j < JB2; j++)
#pragma unroll
            for (int r = 0; r < 4; r++) acc2[i][j][r] = 0.f;

    uint32_t H1b = sbase + OFF_B * 4;
    uint32_t W2b = sbase;
#pragma unroll
    for (int ks = 0; ks < H / 8; ks++) {
        uint32_t afr2[2][4];
#pragma unroll
        for (int i = 0; i < 2; i++) {
            int row = wm * 32 + i * 16 + a_row_in;
            int kq  = ks * 2 + a_kq_hi;
            uint32_t ad = H1b + row * (H * 4) + ((kq ^ (row & 7)) << 4);
            LDSM_X4(afr2[i][0], afr2[i][1], afr2[i][2], afr2[i][3], ad);
        }
        uint32_t bfr2[JB2][2];
#pragma unroll
        for (int jp = 0; jp < JP2; jp++) {
            int n  = wn * (H2 / 2) + jp * 16 + b_row_in;
            int kq = ks * 2 + b_kq_hi;
            uint32_t bd = W2b + n * (H * 4) + ((kq ^ (n & 7)) << 4);
            LDSM_X4(bfr2[2 * jp][0], bfr2[2 * jp][1],
                    bfr2[2 * jp + 1][0], bfr2[2 * jp + 1][1], bd);
        }
#pragma unroll
        for (int i = 0; i < 2; i++)
#pragma unroll
            for (int j = 0; j < JB2; j++) {
                asm volatile(
                    "mma.sync.aligned.m16n8k8.row.col.f32.tf32.tf32.f32 "
                    "{%0,%1,%2,%3}, {%4,%5,%6,%7}, {%8,%9}, {%0,%1,%2,%3};\n"
                    : "+f"(acc2[i][j][0]), "+f"(acc2[i][j][1]),
                      "+f"(acc2[i][j][2]), "+f"(acc2[i][j][3])
                    : "r"(afr2[i][0]), "r"(afr2[i][1]), "r"(afr2[i][2]), "r"(afr2[i][3]),
                      "r"(bfr2[j][0]), "r"(bfr2[j][1]));
            }
    }

    // ---- layer 3: +b2, relu, dot W3, reduce, +b3, scatter ----
    float p[4] = {0.f, 0.f, 0.f, 0.f};
#pragma unroll
    for (int i = 0; i < 2; i++)
#pragma unroll
        for (int j = 0; j < JB2; j++) {
            int col = wn * (H2 / 2) + j * 8 + 2 * (lane & 3);
            float w0 = sW3[col], w1 = sW3[col + 1];
            float c0 = sB2[col], c1 = sB2[col + 1];
            p[i * 2 + 0] += fmaxf(acc2[i][j][0] + c0, 0.f) * w0
                          + fmaxf(acc2[i][j][1] + c1, 0.f) * w1;
            p[i * 2 + 1] += fmaxf(acc2[i][j][2] + c0, 0.f) * w0
                          + fmaxf(acc2[i][j][3] + c1, 0.f) * w1;
        }
#pragma unroll
    for (int t = 0; t < 4; t++) {
        p[t] += __shfl_xor_sync(0xffffffffu, p[t], 1);
        p[t] += __shfl_xor_sync(0xffffffffu, p[t], 2);
    }
    if (wn == 0 && (lane & 3) == 0) {
#pragma unroll
        for (int i = 0; i < 2; i++)
#pragma unroll
            for (int hh = 0; hh < 2; hh++) {
                int m = wm * 32 + i * 16 + hh * 8 + (lane >> 2);
                sPart[m] = p[i * 2 + hh];
            }
    }
    __syncthreads();
    if (wn == 1 && (lane & 3) == 0) {
        float b3v = __ldg(b3);
#pragma unroll
        for (int i = 0; i < 2; i++)
#pragma unroll
            for (int hh = 0; hh < 2; hh++) {
                int m = wm * 32 + i * 16 + hh * 8 + (lane >> 2);
                if (base + m < count)
                    out[sRow[m]] = sPart[m] + p[i * 2 + hh] + b3v;
            }
    }
}

// ---------------- fused kernel ----------------
__global__ __launch_bounds__(NT) void fused_kernel(
    const float* __restrict__ X,
    const float* __restrict__ b1_sc, const float* __restrict__ b2_sc,
    const float* __restrict__ W3_sc, const float* __restrict__ b3_sc,
    const float* __restrict__ b1_st, const float* __restrict__ b2_st,
    const float* __restrict__ W3_st, const float* __restrict__ b3_st,
    const float* __restrict__ b1_wm, const float* __restrict__ b2_wm,
    const float* __restrict__ W3_wm, const float* __restrict__ b3_wm,
    const float* __restrict__ b1_ch, const float* __restrict__ b2_ch,
    const float* __restrict__ W3_ch, const float* __restrict__ b3_ch,
    float* __restrict__ out)
{
    extern __shared__ float smem[];
    int e = blockIdx.x & 3;
    int chunk = blockIdx.x >> 2;
    if (e == 0)
        expert_body<64>(0, chunk, X, g_W1T + (size_t)W1ROW_SC * KDIM, g_W2T + W2OFF_SC,
                        b1_sc, b2_sc, W3_sc, b3_sc, out, smem);
    else if (e == 1)
        expert_body<64>(1, chunk, X, g_W1T + (size_t)W1ROW_ST * KDIM, g_W2T + W2OFF_ST,
                        b1_st, b2_st, W3_st, b3_st, out, smem);
    else if (e == 2)
        expert_body<128>(2, chunk, X, g_W1T + (size_t)W1ROW_WM * KDIM, g_W2T + W2OFF_WM,
                         b1_wm, b2_wm, W3_wm, b3_wm, out, smem);
    else
        expert_body<128>(3, chunk, X, g_W1T + (size_t)W1ROW_CH * KDIM, g_W2T + W2OFF_CH,
                         b1_ch, b2_ch, W3_ch, b3_ch, out, smem);
}

// ---------------- launch ----------------
extern "C" void kernel_launch(void* const* d_in, const int* in_sizes, int n_in,
                              void* d_out, int out_size) {
    const float* x      = (const float*)d_in[0];
    const int*   labels = (const int*)d_in[1];
    const float* W1_sc = (const float*)d_in[2],  *b1_sc = (const float*)d_in[3];
    const float* W2_sc = (const float*)d_in[4],  *b2_sc = (const float*)d_in[5];
    const float* W3_sc = (const float*)d_in[6],  *b3_sc = (const float*)d_in[7];
    const float* W1_st = (const float*)d_in[8],  *b1_st = (const float*)d_in[9];
    const float* W2_st = (const float*)d_in[10], *b2_st = (const float*)d_in[11];
    const float* W3_st = (const float*)d_in[12], *b3_st = (const float*)d_in[13];
    const float* W1_wm = (const float*)d_in[14], *b1_wm = (const float*)d_in[15];
    const float* W2_wm = (const float*)d_in[16], *b2_wm = (const float*)d_in[17];
    const float* W3_wm = (const float*)d_in[18], *b3_wm = (const float*)d_in[19];
    const float* W1_ch = (const float*)d_in[20], *b1_ch = (const float*)d_in[21];
    const float* W2_ch = (const float*)d_in[22], *b2_ch = (const float*)d_in[23];
    const float* W3_ch = (const float*)d_in[24], *b3_ch = (const float*)d_in[25];
    float* out = (float*)d_out;

    zero_cnt_kernel<<<1, 32>>>();
    bucket_kernel<<<NROWS / 256, 256>>>(labels, out);
    prep_kernel<<<768, 256>>>(W1_sc, W1_st, W1_wm, W1_ch,
                              W2_sc, W2_st, W2_wm, W2_ch);

    const size_t smem_bytes = (size_t)SMEM_FLOATS * sizeof(float);  // 198,144 B
    cudaFuncSetAttribute(fused_kernel, cudaFuncAttributeMaxDynamicSharedMemorySize,
                         (int)smem_bytes);

    fused_kernel<<<4 * (NROWS / BM), NT, smem_bytes>>>(x,
        b1_sc, b2_sc, W3_sc, b3_sc,
        b1_st, b2_st, W3_st, b3_st,
        b1_wm, b2_wm, W3_wm, b3_wm,
        b1_ch, b2_ch, W3_ch, b3_ch,
        out);
}

// round 17
// speedup vs baseline: 1.1352x; 1.1352x over previous
#include <cuda_runtime.h>
#include <stdint.h>

#define NROWS 65536
#define KDIM  2048
#define BM 128
#define BK 32
#define NKT (KDIM / BK)   // 64
#define NT  256

// ---------------- device scratch ----------------
__device__ int g_cnt[4];
__device__ int g_perm[4][NROWS];          // 1 MB
__device__ float g_W1T[384 * KDIM];       // 3 MB: W1^T n-major [n][k], tf32 (hedged)
__device__ float g_W2T[20480];            // W2^T n-major [n][k] per expert, tf32

#define W1ROW_SC 0
#define W1ROW_ST 64
#define W1ROW_WM 128
#define W1ROW_CH 256
#define W2OFF_SC 0
#define W2OFF_ST 2048
#define W2OFF_WM 4096
#define W2OFF_CH 12288

// ---------------- helpers ----------------
__device__ __forceinline__ void cp16(uint32_t dst, const float* src) {
    asm volatile("cp.async.cg.shared.global [%0], [%1], 16;\n" :: "r"(dst), "l"(src));
}
__device__ __forceinline__ uint32_t f2tf(float x) {
    uint32_t u; asm("cvt.rna.tf32.f32 %0, %1;" : "=r"(u) : "f"(x)); return u;
}
#define LDSM_X4(R0, R1, R2, R3, ADDR) \
    asm volatile("ldmatrix.sync.aligned.m8n8.x4.shared.b16 {%0,%1,%2,%3}, [%4];" \
        : "=r"(R0), "=r"(R1), "=r"(R2), "=r"(R3) : "r"(ADDR))

// ---------------- prep: transpose + tf32-round W1 (hedged), W2 ----------------
__global__ void prep_kernel(const float* __restrict__ W1_sc, const float* __restrict__ W1_st,
                            const float* __restrict__ W1_wm, const float* __restrict__ W1_ch,
                            const float* __restrict__ W2_sc, const float* __restrict__ W2_st,
                            const float* __restrict__ W2_wm, const float* __restrict__ W2_ch) {
    const int T = 384 * KDIM;
    const float hedge = 1.000244140625f;   // centers tf32-RZ truncation bias of X
    for (int i = blockIdx.x * blockDim.x + threadIdx.x; i < T;
         i += gridDim.x * blockDim.x) {
        int n = i >> 11, k = i & 2047;
        float v;
        if (n < 64)        v = W1_sc[k * 64 + n];
        else if (n < 128)  v = W1_st[k * 64 + (n - 64)];
        else if (n < 256)  v = W1_wm[(size_t)k * 128 + (n - 128)];
        else               v = W1_ch[(size_t)k * 128 + (n - 256)];
        g_W1T[i] = __uint_as_float(f2tf(v * hedge));
    }
    for (int i = blockIdx.x * blockDim.x + threadIdx.x; i < 20480;
         i += gridDim.x * blockDim.x) {
        float v;
        if (i < 2048)       { int j = i;          v = W2_sc[(j & 63) * 32 + (j >> 6)];  }
        else if (i < 4096)  { int j = i - 2048;   v = W2_st[(j & 63) * 32 + (j >> 6)];  }
        else if (i < 12288) { int j = i - 4096;   v = W2_wm[(j & 127) * 64 + (j >> 7)]; }
        else                { int j = i - 12288;  v = W2_ch[(j & 127) * 64 + (j >> 7)]; }
        g_W2T[i] = __uint_as_float(f2tf(v));
    }
}

// ---------------- bucket kernels ----------------
__global__ void zero_cnt_kernel() {
    if (threadIdx.x < 4) g_cnt[threadIdx.x] = 0;
}
__global__ void bucket_kernel(const int* __restrict__ labels, float* __restrict__ out) {
    int r = blockIdx.x * blockDim.x + threadIdx.x;
    if (r >= NROWS) return;
    int lab = labels[r];
    bool valid = (lab >= 0) && (lab <= 3);
    if (!valid) { out[r] = 0.f; lab = -1; }
    int lane = threadIdx.x & 31;
#pragma unroll
    for (int l = 0; l < 4; l++) {
        unsigned mask = __ballot_sync(0xffffffffu, lab == l);
        if (lab == l) {
            int leader = __ffs(mask) - 1;
            int myrank = __popc(mask & ((1u << lane) - 1));
            int basep = 0;
            if (lane == leader) basep = atomicAdd(&g_cnt[l], __popc(mask));
            basep = __shfl_sync(mask, basep, leader);
            g_perm[l][basep + myrank] = r;
        }
    }
}

// smem (floats): A 4x4096 [0,16384) | B 4x(H*32) [16384,+4*BBUF) | tail @32768 (384)
// W2T aliases A stages 0..1 (dead when loaded at kt=NKT-1); h1 aliases B-stage region.
#define OFF_B 16384
#define OFF_TAIL 32768
#define SMEM_FLOATS 33152     // 132,608 B -> 1 CTA/SM

// ---------------- fused expert body (256 thr, 8 warps = 4m x 2n, LDSM, 4-stage) --------
template<int H>
__device__ __forceinline__ void expert_body(
    int e, int chunk, const float* __restrict__ X,
    const float* __restrict__ W1T,   // [H rows][2048], tf32 hedged
    const float* __restrict__ W2T,   // [H2 rows][H], tf32
    const float* __restrict__ b1, const float* __restrict__ b2,
    const float* __restrict__ W3, const float* __restrict__ b3,
    float* __restrict__ out, float* smem)
{
    constexpr int H2   = H / 2;
    constexpr int JB   = H / 16;     // layer-1 n8 blocks/warp (warp n-tile H/2)
    constexpr int JP   = H / 32;     // x4-LDSM pairs
    constexpr int JB2  = H2 / 16;
    constexpr int JP2  = H2 / 32;
    constexpr int ABUF = 4096;
    constexpr int BBUF = H * 32;

    int count = g_cnt[e];
    int base = chunk * BM;
    if (base >= count) return;
    const int* perm = g_perm[e];

    uint32_t sbase = (uint32_t)__cvta_generic_to_shared(smem);
    float* sW3   = smem + OFF_TAIL;
    float* sB2   = smem + OFF_TAIL + 64;
    float* sPart = smem + OFF_TAIL + 128;
    int*   sRow  = (int*)(smem + OFF_TAIL + 256);

    int tid = threadIdx.x, lane = tid & 31, warp = tid >> 5;
    int wm = warp & 3;        // 32 rows each
    int wn = warp >> 2;       // 0..1, H/2 cols each

    if (tid < BM) {
        int idx = base + tid;
        if (idx >= count) idx = count - 1;
        sRow[tid] = perm[idx];
    }
    if (tid < H2) { sW3[tid] = W3[tid]; sB2[tid] = b2[tid]; }
    __syncthreads();

    int rid[4];
#pragma unroll
    for (int it = 0; it < 4; it++) rid[it] = sRow[(tid + it * NT) >> 3];

    float acc[2][JB][4];
#pragma unroll
    for (int i = 0; i < 2; i++)
#pragma unroll
        for (int j = 0; j < JB; j++)
#pragma unroll
            for (int r = 0; r < 4; r++) acc[i][j][r] = 0.f;

    auto loadA = [&](int buf, int kt) {
        uint32_t dbase = sbase + buf * (ABUF * 4);
#pragma unroll
        for (int it = 0; it < 4; it++) {
            int slot = tid + it * NT;
            int r = slot >> 3, c = slot & 7;
            cp16(dbase + r * 128 + ((c ^ (r & 7)) << 4),
                 X + (size_t)rid[it] * KDIM + kt * BK + c * 4);
        }
    };
    auto loadB = [&](int buf, int kt) {
        uint32_t dbase = sbase + (OFF_B + buf * BBUF) * 4;
#pragma unroll
        for (int it = 0; it < (H * 8) / NT; it++) {
            int slot = tid + it * NT;
            int r = slot >> 3, c = slot & 7;
            cp16(dbase + r * 128 + ((c ^ (r & 7)) << 4),
                 W1T + (size_t)r * KDIM + kt * BK + c * 4);
        }
    };
    auto loadW2 = [&]() {     // into A stages 0..1 (smem base)
        constexpr int CQ = H / 4;
#pragma unroll
        for (int it = 0; it < (H2 * CQ) / NT; it++) {
            int slot = tid + it * NT;
            int r = slot / CQ, c = slot % CQ;
            cp16(sbase + r * (H * 4) + ((c ^ (r & 7)) << 4),
                 W2T + (size_t)r * H + c * 4);
        }
    };

    // 4-stage prologue
    loadA(0, 0); loadB(0, 0);
    asm volatile("cp.async.commit_group;\n");
    loadA(1, 1); loadB(1, 1);
    asm volatile("cp.async.commit_group;\n");
    loadA(2, 2); loadB(2, 2);
    asm volatile("cp.async.commit_group;\n");

    int a_row_in = ((lane >> 3) & 1) * 8 + (lane & 7);
    int a_kq_hi  = lane >> 4;
    int b_row_in = ((lane >> 4) & 1) * 8 + (lane & 7);
    int b_kq_hi  = (lane >> 3) & 1;

    // R12 ordering (correct): wait for group kt, barrier (publishes all threads'
    // copies + frees stage (kt-1)%4), THEN prefetch kt+3, THEN compute kt.
    for (int kt = 0; kt < NKT; kt++) {
        int buf = kt & 3;
        if (kt <= NKT - 3) {
            asm volatile("cp.async.wait_group 2;\n");
        } else if (kt == NKT - 2) {
            asm volatile("cp.async.wait_group 1;\n");
        } else {
            asm volatile("cp.async.wait_group 0;\n");
        }
        __syncthreads();
        if (kt + 3 < NKT) {
            int nb = (kt + 3) & 3;
            loadA(nb, kt + 3);
            loadB(nb, kt + 3);
            asm volatile("cp.async.commit_group;\n");
        } else if (kt == NKT - 1) {
            loadW2();                                   // A stages 0,1 are dead now
            asm volatile("cp.async.commit_group;\n");
        }

        uint32_t Ab = sbase + buf * (ABUF * 4);
        uint32_t Bb = sbase + (OFF_B + buf * BBUF) * 4;

#pragma unroll
        for (int ks = 0; ks < 4; ks++) {
            uint32_t afr[2][4];
#pragma unroll
            for (int i = 0; i < 2; i++) {
                int row = wm * 32 + i * 16 + a_row_in;
                int kq  = ks * 2 + a_kq_hi;
                uint32_t ad = Ab + row * 128 + ((kq ^ (row & 7)) << 4);
                LDSM_X4(afr[i][0], afr[i][1], afr[i][2], afr[i][3], ad);
            }
            uint32_t bfr[JB][2];
#pragma unroll
            for (int jp = 0; jp < JP; jp++) {
                int n  = wn * (H / 2) + jp * 16 + b_row_in;
                int kq = ks * 2 + b_kq_hi;
                uint32_t bd = Bb + n * 128 + ((kq ^ (n & 7)) << 4);
                LDSM_X4(bfr[2 * jp][0], bfr[2 * jp][1],
                        bfr[2 * jp + 1][0], bfr[2 * jp + 1][1], bd);
            }
#pragma unroll
            for (int i = 0; i < 2; i++)
#pragma unroll
                for (int j = 0; j < JB; j++) {
                    asm volatile(
                        "mma.sync.aligned.m16n8k8.row.col.f32.tf32.tf32.f32 "
                        "{%0,%1,%2,%3}, {%4,%5,%6,%7}, {%8,%9}, {%0,%1,%2,%3};\n"
                        : "+f"(acc[i][j][0]), "+f"(acc[i][j][1]),
                          "+f"(acc[i][j][2]), "+f"(acc[i][j][3])
                        : "r"(afr[i][0]), "r"(afr[i][1]), "r"(afr[i][2]), "r"(afr[i][3]),
                          "r"(bfr[j][0]), "r"(bfr[j][1]));
                }
        }
    }
    __syncthreads();   // all compute done before h1 overwrites B stages

    // ---- layer-1 epilogue: +b1, relu, tf32-round (rna), h1 -> B-stage region ----
    float* h1 = smem + OFF_B;
#pragma unroll
    for (int i = 0; i < 2; i++) {
        int row0 = wm * 32 + i * 16 + (lane >> 2);
        int row1 = row0 + 8;
#pragma unroll
        for (int j = 0; j < JB; j++) {
            int col = wn * (H / 2) + j * 8 + 2 * (lane & 3);
            float bv0 = __ldg(b1 + col), bv1 = __ldg(b1 + col + 1);
            float2 v0, v1;
            v0.x = __uint_as_float(f2tf(fmaxf(acc[i][j][0] + bv0, 0.f)));
            v0.y = __uint_as_float(f2tf(fmaxf(acc[i][j][1] + bv1, 0.f)));
            v1.x = __uint_as_float(f2tf(fmaxf(acc[i][j][2] + bv0, 0.f)));
            v1.y = __uint_as_float(f2tf(fmaxf(acc[i][j][3] + bv1, 0.f)));
            int cq = col >> 2, cr = col & 3;
            *(float2*)((char*)h1 + row0 * (H * 4) + ((cq ^ (row0 & 7)) << 4) + cr * 4) = v0;
            *(float2*)((char*)h1 + row1 * (H * 4) + ((cq ^ (row1 & 7)) << 4) + cr * 4) = v1;
        }
    }
    asm volatile("cp.async.wait_group 0;\n");   // W2T landed (A stages 0..1)
    __syncthreads();

    // ---- layer 2: acc2 = h1 @ W2T^T (LDSM + mma; operands exact tf32) ----
    float acc2[2][JB2][4];
#pragma unroll
    for (int i = 0; i < 2; i++)
#pragma unroll
        for (int j = 0; j < JB2; j++)
#pragma unroll
            for (int r = 0; r < 4; r++) acc2[i][j][r] = 0.f;

    uint32_t H1b = sbase + OFF_B * 4;
    uint32_t W2b = sbase;
#pragma unroll
    for (int ks = 0; ks < H / 8; ks++) {
        uint32_t afr2[2][4];
#pragma unroll
        for (int i = 0; i < 2; i++) {
            int row = wm * 32 + i * 16 + a_row_in;
            int kq  = ks * 2 + a_kq_hi;
            uint32_t ad = H1b + row * (H * 4) + ((kq ^ (row & 7)) << 4);
            LDSM_X4(afr2[i][0], afr2[i][1], afr2[i][2], afr2[i][3], ad);
        }
        uint32_t bfr2[JB2][2];
#pragma unroll
        for (int jp = 0; jp < JP2; jp++) {
            int n  = wn * (H2 / 2) + jp * 16 + b_row_in;
            int kq = ks * 2 + b_kq_hi;
            uint32_t bd = W2b + n * (H * 4) + ((kq ^ (n & 7)) << 4);
            LDSM_X4(bfr2[2 * jp][0], bfr2[2 * jp][1],
                    bfr2[2 * jp + 1][0], bfr2[2 * jp + 1][1], bd);
        }
#pragma unroll
        for (int i = 0; i < 2; i++)
#pragma unroll
            for (int j = 0; j < JB2; j++) {
                asm volatile(
                    "mma.sync.aligned.m16n8k8.row.col.f32.tf32.tf32.f32 "
                    "{%0,%1,%2,%3}, {%4,%5,%6,%7}, {%8,%9}, {%0,%1,%2,%3};\n"
                    : "+f"(acc2[i][j][0]), "+f"(acc2[i][j][1]),
                      "+f"(acc2[i][j][2]), "+f"(acc2[i][j][3])
                    : "r"(afr2[i][0]), "r"(afr2[i][1]), "r"(afr2[i][2]), "r"(afr2[i][3]),
                      "r"(bfr2[j][0]), "r"(bfr2[j][1]));
            }
    }

    // ---- layer 3: +b2, relu, dot W3, reduce, +b3, scatter ----
    float p[4] = {0.f, 0.f, 0.f, 0.f};
#pragma unroll
    for (int i = 0; i < 2; i++)
#pragma unroll
        for (int j = 0; j < JB2; j++) {
            int col = wn * (H2 / 2) + j * 8 + 2 * (lane & 3);
            float w0 = sW3[col], w1 = sW3[col + 1];
            float c0 = sB2[col], c1 = sB2[col + 1];
            p[i * 2 + 0] += fmaxf(acc2[i][j][0] + c0, 0.f) * w0
                          + fmaxf(acc2[i][j][1] + c1, 0.f) * w1;
            p[i * 2 + 1] += fmaxf(acc2[i][j][2] + c0, 0.f) * w0
                          + fmaxf(acc2[i][j][3] + c1, 0.f) * w1;
        }
#pragma unroll
    for (int t = 0; t < 4; t++) {
        p[t] += __shfl_xor_sync(0xffffffffu, p[t], 1);
        p[t] += __shfl_xor_sync(0xffffffffu, p[t], 2);
    }
    if (wn == 0 && (lane & 3) == 0) {
#pragma unroll
        for (int i = 0; i < 2; i++)
#pragma unroll
            for (int hh = 0; hh < 2; hh++) {
                int m = wm * 32 + i * 16 + hh * 8 + (lane >> 2);
                sPart[m] = p[i * 2 + hh];
            }
    }
    __syncthreads();
    if (wn == 1 && (lane & 3) == 0) {
        float b3v = __ldg(b3);
#pragma unroll
        for (int i = 0; i < 2; i++)
#pragma unroll
            for (int hh = 0; hh < 2; hh++) {
                int m = wm * 32 + i * 16 + hh * 8 + (lane >> 2);
                if (base + m < count)
                    out[sRow[m]] = sPart[m] + p[i * 2 + hh] + b3v;
            }
    }
}

// ---------------- fused kernel ----------------
__global__ __launch_bounds__(NT) void fused_kernel(
    const float* __restrict__ X,
    const float* __restrict__ b1_sc, const float* __restrict__ b2_sc,
    const float* __restrict__ W3_sc, const float* __restrict__ b3_sc,
    const float* __restrict__ b1_st, const float* __restrict__ b2_st,
    const float* __restrict__ W3_st, const float* __restrict__ b3_st,
    const float* __restrict__ b1_wm, const float* __restrict__ b2_wm,
    const float* __restrict__ W3_wm, const float* __restrict__ b3_wm,
    const float* __restrict__ b1_ch, const float* __restrict__ b2_ch,
    const float* __restrict__ W3_ch, const float* __restrict__ b3_ch,
    float* __restrict__ out)
{
    extern __shared__ float smem[];
    int e = blockIdx.x & 3;
    int chunk = blockIdx.x >> 2;
    if (e == 0)
        expert_body<64>(0, chunk, X, g_W1T + (size_t)W1ROW_SC * KDIM, g_W2T + W2OFF_SC,
                        b1_sc, b2_sc, W3_sc, b3_sc, out, smem);
    else if (e == 1)
        expert_body<64>(1, chunk, X, g_W1T + (size_t)W1ROW_ST * KDIM, g_W2T + W2OFF_ST,
                        b1_st, b2_st, W3_st, b3_st, out, smem);
    else if (e == 2)
        expert_body<128>(2, chunk, X, g_W1T + (size_t)W1ROW_WM * KDIM, g_W2T + W2OFF_WM,
                         b1_wm, b2_wm, W3_wm, b3_wm, out, smem);
    else
        expert_body<128>(3, chunk, X, g_W1T + (size_t)W1ROW_CH * KDIM, g_W2T + W2OFF_CH,
                         b1_ch, b2_ch, W3_ch, b3_ch, out, smem);
}

// ---------------- launch ----------------
extern "C" void kernel_launch(void* const* d_in, const int* in_sizes, int n_in,
                              void* d_out, int out_size) {
    const float* x      = (const float*)d_in[0];
    const int*   labels = (const int*)d_in[1];
    const float* W1_sc = (const float*)d_in[2],  *b1_sc = (const float*)d_in[3];
    const float* W2_sc = (const float*)d_in[4],  *b2_sc = (const float*)d_in[5];
    const float* W3_sc = (const float*)d_in[6],  *b3_sc = (const float*)d_in[7];
    const float* W1_st = (const float*)d_in[8],  *b1_st = (const float*)d_in[9];
    const float* W2_st = (const float*)d_in[10], *b2_st = (const float*)d_in[11];
    const float* W3_st = (const float*)d_in[12], *b3_st = (const float*)d_in[13];
    const float* W1_wm = (const float*)d_in[14], *b1_wm = (const float*)d_in[15];
    const float* W2_wm = (const float*)d_in[16], *b2_wm = (const float*)d_in[17];
    const float* W3_wm = (const float*)d_in[18], *b3_wm = (const float*)d_in[19];
    const float* W1_ch = (const float*)d_in[20], *b1_ch = (const float*)d_in[21];
    const float* W2_ch = (const float*)d_in[22], *b2_ch = (const float*)d_in[23];
    const float* W3_ch = (const float*)d_in[24], *b3_ch = (const float*)d_in[25];
    float* out = (float*)d_out;

    zero_cnt_kernel<<<1, 32>>>();
    bucket_kernel<<<NROWS / 256, 256>>>(labels, out);
    prep_kernel<<<768, 256>>>(W1_sc, W1_st, W1_wm, W1_ch,
                              W2_sc, W2_st, W2_wm, W2_ch);

    const size_t smem_bytes = (size_t)SMEM_FLOATS * sizeof(float);  // 132,608 B
    cudaFuncSetAttribute(fused_kernel, cudaFuncAttributeMaxDynamicSharedMemorySize,
                         (int)smem_bytes);

    fused_kernel<<<4 * (NROWS / BM), NT, smem_bytes>>>(x,
        b1_sc, b2_sc, W3_sc, b3_sc,
        b1_st, b2_st, W3_st, b3_st,
        b1_wm, b2_wm, W3_wm, b3_wm,
        b1_ch, b2_ch, W3_ch, b3_ch,
        out);
}